// round 6
// baseline (speedup 1.0000x reference)
#include <cuda_runtime.h>
#include <math.h>

#define NB 256
#define IH 144
#define IW 256
#define HR 144
#define WR 256
#define F 16
#define D 128
#define BPT 4   // batches per block (sample kernel)

#define FOV_HALF 0.654498469497874f   // 0.5 * 75deg in rad
#define GELU_GAMMA 1.7015043497085571f

// Scratch (no allocations allowed)
__device__ float2 g_dirq[HR * WR];     // homography coords q = d.xy / d.z
__device__ float  g_rm[NB * 12];       // rotation matrices, padded to 12 floats
                                       // (row 2 pre-scaled by 1/128)

__device__ __forceinline__ float gelu_tanh(float x) {
    // matches jax.nn.gelu(approximate=True)
    float x3 = x * x * x;
    float inner = 0.7978845608028654f * (x + 0.044715f * x3);
    float t = tanhf(inner);
    return 0.5f * x * (1.0f + t);
}

// ---------------------------------------------------------------------------
// Kernel 1 (merged): blocks [0, HR) build the q table; blocks [HR, HR+NB)
// run the per-batch MLP -> Euler angles -> rotation matrix.
// ---------------------------------------------------------------------------
__global__ void setup_kernel(const float* __restrict__ persp,
                             const float* __restrict__ W1, const float* __restrict__ b1,
                             const float* __restrict__ W2, const float* __restrict__ b2,
                             const float* __restrict__ Wp, const float* __restrict__ bp) {
    if (blockIdx.x < HR) {
        // ---- q table: d = (sinc*ax, sinc*ay, cos a); q = d.xy / cos a ----
        int w = threadIdx.x;
        int h = blockIdx.x;
        float gx = ((float)(2 * w + 1 - WR)) * (1.0f / 256.0f);
        float gy = ((float)(2 * h + 1 - HR)) * (1.0f / 256.0f);
        float ax = gx * FOV_HALF;
        float ay = gy * FOV_HALF;
        float a = sqrtf(ax * ax + ay * ay) + 1e-12f;
        float s, c;
        sincosf(a, &s, &c);
        float t = s / (a * c);          // tan(a)/a   (a < 0.75 rad, c > 0.7)
        g_dirq[h * WR + w] = make_float2(t * ax, t * ay);
        return;
    }

    // ---- MLP ----
    __shared__ float sp[F];
    __shared__ float h1[D];
    __shared__ float h2[D];
    __shared__ float sang[3];

    int n = blockIdx.x - HR;
    int tid = threadIdx.x;

    if (tid < F) sp[tid] = persp[n * F + tid];
    __syncthreads();

    if (tid < D) {
        float acc = b1[tid];
#pragma unroll
        for (int k = 0; k < F; k++)
            acc = fmaf(sp[k], __ldg(&W1[k * D + tid]), acc);
        h1[tid] = gelu_tanh(acc) * GELU_GAMMA;
    }
    __syncthreads();

    if (tid < D) {
        float acc2 = b2[tid];
#pragma unroll 8
        for (int k = 0; k < D; k++)
            acc2 = fmaf(h1[k], __ldg(&W2[k * D + tid]), acc2);
        h2[tid] = gelu_tanh(acc2) * GELU_GAMMA;
    }
    __syncthreads();

    if (tid < 3) {
        float a = bp[tid];
        for (int k = 0; k < D; k++)
            a = fmaf(h2[k], __ldg(&Wp[k * 3 + tid]), a);
        sang[tid] = a;
    }
    __syncthreads();

    if (tid == 0) {
        float axr = sang[0], ayr = sang[1], azr = sang[2];
        float cx, sx, cy, sy, cz, sz;
        sincosf(axr, &sx, &cx);
        sincosf(ayr, &sy, &cy);
        sincosf(azr, &sz, &cz);
        // R = Rz @ Ry @ Rx ; row 2 pre-scaled by 1/128 so px = rx/rz128 + 127.5
        float* r = &g_rm[n * 12];
        r[0]  = cz * cy;
        r[1]  = cz * sy * sx - sz * cx;
        r[2]  = cz * sy * cx + sz * sx;
        r[3]  = 0.0f;
        r[4]  = sz * cy;
        r[5]  = sz * sy * sx + cz * cx;
        r[6]  = sz * sy * cx - cz * sx;
        r[7]  = 0.0f;
        r[8]  = -sy     * 0.0078125f;
        r[9]  = cy * sx * 0.0078125f;
        r[10] = cy * cx * 0.0078125f;
        r[11] = 0.0f;
    }
}

// ---------------------------------------------------------------------------
// Kernel 2: rotate rays (homography form), project, bilinear sample.
//   Rotation coefficients live in 2 registers per lane (48 floats / warp,
//   preloaded via 2 coalesced LDGs) and are broadcast with compile-time-index
//   __shfl_sync — zero L1TEX traffic for coefficients, no smem, no barrier.
//   grid = (HR, NB/BPT), block = 256
// ---------------------------------------------------------------------------

// idx = 12*b + j, compile-time constant after unrolling
#define COEF(b, j) ((12 * (b) + (j)) < 32 \
    ? __shfl_sync(0xffffffffu, cLo, 12 * (b) + (j)) \
    : __shfl_sync(0xffffffffu, cHi, 12 * (b) + (j) - 32))

__global__ void __launch_bounds__(256) sample_kernel(const float* __restrict__ stim,
                                                     float* __restrict__ out) {
    int w = threadIdx.x;
    int h = blockIdx.x;
    int nb = blockIdx.y * BPT;
    int lane = w & 31;

    // preload 48 coefficients into 2 regs/lane (lanes 16..31 of cHi duplicate)
    const float* rmp = &g_rm[nb * 12];
    float cLo = __ldg(rmp + lane);
    float cHi = __ldg(rmp + 32 + (lane & 15));

    float2 q = g_dirq[h * WR + w];

    const float* img = stim + (size_t)nb * (IH * IW);
    float* outp = out + ((size_t)nb * IH + h) * IW + w;

#pragma unroll
    for (int b = 0; b < BPT; b++) {
        float r0 = COEF(b, 0), r1 = COEF(b, 1), r2 = COEF(b, 2);
        float r3 = COEF(b, 4), r4 = COEF(b, 5), r5 = COEF(b, 6);
        float r6 = COEF(b, 8), r7 = COEF(b, 9), r8 = COEF(b, 10);

        float rx = fmaf(r0, q.x, fmaf(r1, q.y, r2));
        float ry = fmaf(r3, q.x, fmaf(r4, q.y, r5));
        float rz = fmaf(r6, q.x, fmaf(r7, q.y, r8));      // true rz / 128

        bool safe = rz > 7.8125e-6f;                      // 0.001/128
        float inv = __fdividef(1.0f, rz);
        float px = safe ? fmaf(rx, inv, 127.5f) : 1.0e8f;
        float py = safe ? fmaf(ry, inv, 71.5f)  : 1.0e8f;

        float x0f = floorf(px);
        float y0f = floorf(py);
        float wx = px - x0f;
        float wy = py - y0f;
        int x0 = (int)x0f;
        int y0 = (int)y0f;

        bool vx0 = (unsigned)x0 < (unsigned)IW;
        bool vx1 = (unsigned)(x0 + 1) < (unsigned)IW;
        bool vy0 = (unsigned)y0 < (unsigned)IH;
        bool vy1 = (unsigned)(y0 + 1) < (unsigned)IH;

        // single base; invalid corners are predicated off — no clamping.
        int base = y0 * IW + x0;
        float v00 = (vy0 && vx0) ? __ldg(img + base)          : 0.0f;
        float v01 = (vy0 && vx1) ? __ldg(img + base + 1)      : 0.0f;
        float v10 = (vy1 && vx0) ? __ldg(img + base + IW)     : 0.0f;
        float v11 = (vy1 && vx1) ? __ldg(img + base + IW + 1) : 0.0f;

        float top = fmaf(wx, v01 - v00, v00);
        float bot = fmaf(wx, v11 - v10, v10);
        outp[(size_t)b * (IH * IW)] = fmaf(wy, bot - top, top);

        img += IH * IW;
    }
}

// ---------------------------------------------------------------------------
extern "C" void kernel_launch(void* const* d_in, const int* in_sizes, int n_in,
                              void* d_out, int out_size) {
    const float* stimulus = (const float*)d_in[0];
    const float* persp    = (const float*)d_in[1];
    const float* W1       = (const float*)d_in[2];
    const float* b1       = (const float*)d_in[3];
    const float* W2       = (const float*)d_in[4];
    const float* b2       = (const float*)d_in[5];
    const float* Wp       = (const float*)d_in[6];
    const float* bp       = (const float*)d_in[7];
    float* out = (float*)d_out;

    setup_kernel<<<HR + NB, WR>>>(persp, W1, b1, W2, b2, Wp, bp);
    sample_kernel<<<dim3(HR, NB / BPT), 256>>>(stimulus, out);
}

// round 7
// speedup vs baseline: 1.1298x; 1.1298x over previous
#include <cuda_runtime.h>
#include <math.h>

#define NB 256
#define IH 144
#define IW 256
#define HR 144
#define WR 256
#define F 16
#define D 128
#define RPB 16  // rows per block (sample kernel)

#define FOV_HALF 0.654498469497874f   // 0.5 * 75deg in rad
#define GELU_GAMMA 1.7015043497085571f

// Scratch (no allocations allowed)
__device__ float2 g_dirq[HR * WR];     // homography coords q = d.xy / d.z
__device__ float  g_rm[NB * 12];       // rotation matrices, padded to 12 floats
                                       // (row 2 pre-scaled by 1/128)

__device__ __forceinline__ float gelu_tanh(float x) {
    // matches jax.nn.gelu(approximate=True)
    float x3 = x * x * x;
    float inner = 0.7978845608028654f * (x + 0.044715f * x3);
    float t = tanhf(inner);
    return 0.5f * x * (1.0f + t);
}

// ---------------------------------------------------------------------------
// Kernel 1 (merged): blocks [0, HR) build the q table; blocks [HR, HR+NB)
// run the per-batch MLP -> Euler angles -> rotation matrix.
// ---------------------------------------------------------------------------
__global__ void setup_kernel(const float* __restrict__ persp,
                             const float* __restrict__ W1, const float* __restrict__ b1,
                             const float* __restrict__ W2, const float* __restrict__ b2,
                             const float* __restrict__ Wp, const float* __restrict__ bp) {
    if (blockIdx.x < HR) {
        // ---- q table: d = (sinc*ax, sinc*ay, cos a); q = d.xy / cos a ----
        int w = threadIdx.x;
        int h = blockIdx.x;
        float gx = ((float)(2 * w + 1 - WR)) * (1.0f / 256.0f);
        float gy = ((float)(2 * h + 1 - HR)) * (1.0f / 256.0f);
        float ax = gx * FOV_HALF;
        float ay = gy * FOV_HALF;
        float a = sqrtf(ax * ax + ay * ay) + 1e-12f;
        float s, c;
        sincosf(a, &s, &c);
        float t = s / (a * c);          // tan(a)/a   (a < 0.75 rad, c > 0.7)
        g_dirq[h * WR + w] = make_float2(t * ax, t * ay);
        return;
    }

    // ---- MLP ----
    __shared__ float sp[F];
    __shared__ float h1[D];
    __shared__ float h2[D];
    __shared__ float sang[3];

    int n = blockIdx.x - HR;
    int tid = threadIdx.x;

    if (tid < F) sp[tid] = persp[n * F + tid];
    __syncthreads();

    if (tid < D) {
        float acc = b1[tid];
#pragma unroll
        for (int k = 0; k < F; k++)
            acc = fmaf(sp[k], __ldg(&W1[k * D + tid]), acc);
        h1[tid] = gelu_tanh(acc) * GELU_GAMMA;
    }
    __syncthreads();

    if (tid < D) {
        float acc2 = b2[tid];
#pragma unroll 8
        for (int k = 0; k < D; k++)
            acc2 = fmaf(h1[k], __ldg(&W2[k * D + tid]), acc2);
        h2[tid] = gelu_tanh(acc2) * GELU_GAMMA;
    }
    __syncthreads();

    if (tid < 3) {
        float a = bp[tid];
        for (int k = 0; k < D; k++)
            a = fmaf(h2[k], __ldg(&Wp[k * 3 + tid]), a);
        sang[tid] = a;
    }
    __syncthreads();

    if (tid == 0) {
        float axr = sang[0], ayr = sang[1], azr = sang[2];
        float cx, sx, cy, sy, cz, sz;
        sincosf(axr, &sx, &cx);
        sincosf(ayr, &sy, &cy);
        sincosf(azr, &sz, &cz);
        // R = Rz @ Ry @ Rx ; row 2 pre-scaled by 1/128 so px = rx/rz128 + 127.5
        float* r = &g_rm[n * 12];
        r[0]  = cz * cy;
        r[1]  = cz * sy * sx - sz * cx;
        r[2]  = cz * sy * cx + sz * sx;
        r[3]  = 0.0f;
        r[4]  = sz * cy;
        r[5]  = sz * sy * sx + cz * cx;
        r[6]  = sz * sy * cx - cz * sx;
        r[7]  = 0.0f;
        r[8]  = -sy     * 0.0078125f;
        r[9]  = cy * sx * 0.0078125f;
        r[10] = cy * cx * 0.0078125f;
        r[11] = 0.0f;
    }
}

// ---------------------------------------------------------------------------
// Kernel 2: rotate rays (homography form), project, bilinear sample.
//   Inverted loop nest: one batch per block, RPB=16 rows per block. The 9
//   rotation coefficients live in registers for the whole block (9 uniform
//   LDGs per block, ~0.6 L1 instr per warp-iter instead of 9 LDS) — cuts
//   L1TEX instruction count per warp-iter from ~15 to ~6.6.
//   grid = (HR/RPB, NB), block = 256 (one full row per iteration)
// ---------------------------------------------------------------------------
__global__ void __launch_bounds__(256, 6) sample_kernel(const float* __restrict__ stim,
                                                        float* __restrict__ out) {
    int w = threadIdx.x;
    int h0 = blockIdx.x * RPB;
    int n = blockIdx.y;

    // rotation coefficients: block-uniform, registers for the whole kernel
    const float* rmp = &g_rm[n * 12];
    float r0 = __ldg(rmp + 0), r1 = __ldg(rmp + 1), r2 = __ldg(rmp + 2);
    float r3 = __ldg(rmp + 4), r4 = __ldg(rmp + 5), r5 = __ldg(rmp + 6);
    float r6 = __ldg(rmp + 8), r7 = __ldg(rmp + 9), r8 = __ldg(rmp + 10);

    const float* img = stim + (size_t)n * (IH * IW);
    float* outp = out + ((size_t)n * IH + h0) * IW + w;
    const float2* qp = &g_dirq[h0 * WR + w];

#pragma unroll 4
    for (int i = 0; i < RPB; i++) {
        float2 q = qp[i * WR];

        float rx = fmaf(r0, q.x, fmaf(r1, q.y, r2));
        float ry = fmaf(r3, q.x, fmaf(r4, q.y, r5));
        float rz = fmaf(r6, q.x, fmaf(r7, q.y, r8));      // true rz / 128

        bool safe = rz > 7.8125e-6f;                      // 0.001/128
        float inv = __fdividef(1.0f, rz);
        float px = safe ? fmaf(rx, inv, 127.5f) : 1.0e8f;
        float py = safe ? fmaf(ry, inv, 71.5f)  : 1.0e8f;

        float x0f = floorf(px);
        float y0f = floorf(py);
        float wx = px - x0f;
        float wy = py - y0f;
        int x0 = (int)x0f;
        int y0 = (int)y0f;

        bool vx0 = (unsigned)x0 < (unsigned)IW;
        bool vx1 = (unsigned)(x0 + 1) < (unsigned)IW;
        bool vy0 = (unsigned)y0 < (unsigned)IH;
        bool vy1 = (unsigned)(y0 + 1) < (unsigned)IH;

        // single base; invalid corners are predicated off — no clamping.
        int base = y0 * IW + x0;
        float v00 = (vy0 && vx0) ? __ldg(img + base)          : 0.0f;
        float v01 = (vy0 && vx1) ? __ldg(img + base + 1)      : 0.0f;
        float v10 = (vy1 && vx0) ? __ldg(img + base + IW)     : 0.0f;
        float v11 = (vy1 && vx1) ? __ldg(img + base + IW + 1) : 0.0f;

        float top = fmaf(wx, v01 - v00, v00);
        float bot = fmaf(wx, v11 - v10, v10);
        outp[i * IW] = fmaf(wy, bot - top, top);
    }
}

// ---------------------------------------------------------------------------
extern "C" void kernel_launch(void* const* d_in, const int* in_sizes, int n_in,
                              void* d_out, int out_size) {
    const float* stimulus = (const float*)d_in[0];
    const float* persp    = (const float*)d_in[1];
    const float* W1       = (const float*)d_in[2];
    const float* b1       = (const float*)d_in[3];
    const float* W2       = (const float*)d_in[4];
    const float* b2       = (const float*)d_in[5];
    const float* Wp       = (const float*)d_in[6];
    const float* bp       = (const float*)d_in[7];
    float* out = (float*)d_out;

    setup_kernel<<<HR + NB, WR>>>(persp, W1, b1, W2, b2, Wp, bp);
    sample_kernel<<<dim3(HR / RPB, NB), 256>>>(stimulus, out);
}